// round 17
// baseline (speedup 1.0000x reference)
#include <cuda_runtime.h>
#include <cuda_bf16.h>
#include <cstdint>

// Problem constants
#define Hn 1024
#define Bn 128
#define Tn 400
#define Sn 64
#define Cn 8
#define NOUTn 3
#define NCLSn 3
#define BOTn 2
#define CLSOUTn 8
#define NEXC 819              // int(1024 * 0.8)

#define NCTA 128
#define NTHR 256
#define NBC 4                 // batch groups (32 b each)

#define ALPHA_N 0.2f
#define DT_SEC 0.02f
#define NZ_SCALE 0.25f        // NOISE_STD / ALPHA_N
#define AX_SLOW ((float)(20.0 / 1500.0))
#define AX_FAST ((float)(20.0 / 200.0))

#define NR (NOUTn + NCLSn * CLSOUTn)   // 27 fused readout rows
#define PR_ROWS 32
#define CPITCH 33

#define HPITCH 516            // padded h row: 512 kq words + 4 (bank shift 4)
#define CHUNK_BYTES (16 * HPITCH * 4)   // 33024 B = 16 rows

// smem layout (words):
//  wh [512 kq][32 j] swizzled : 16384
//  wl                          : 16384
//  bufA (16 rows x 516)        :  8256   at 32768
//  bufB                        :  8256   at 41024
//  mbarriers (2 x u64)         :     4   at 49280
//  (Cbuf 8448 words aliases bufA+; P3 comb 27648 aliases everything)
#define SM_WH 0
#define SM_WL 16384
#define SM_ST 32768
#define SM_BUFB (32768 + 8256)
#define SM_MBAR 49280
#define SM_COMB 0
#define SMEM_WORDS 49288
#define SMEM_BYTES (SMEM_WORDS * 4)

// ---------------- device scratch ----------------
__device__ float g_drive[(size_t)Tn * Hn * Bn];   // [t][h][b], noise folded
__device__ unsigned g_hph[2][Bn * HPITCH];        // h_post hi pairs, b-major padded
__device__ unsigned g_hpl[2][Bn * HPITCH];        // h_post lo pairs
__device__ float g_comb[NR * Hn];
__device__ float g_combb[NR];
__device__ unsigned g_count;                      // phase-transition counter
__device__ unsigned g_hbc[NBC * 32];              // h-ready per batch-group (32/step)

// ---------------- sync helpers ----------------
__device__ __forceinline__ void red_rel(unsigned* p) {
    asm volatile("red.release.gpu.global.add.u32 [%0], 1;" :: "l"(p) : "memory");
}
__device__ __forceinline__ unsigned ld_rlx(const unsigned* p) {
    unsigned v;
    asm volatile("ld.relaxed.gpu.global.u32 %0, [%1];" : "=r"(v) : "l"(p) : "memory");
    return v;
}
__device__ __forceinline__ void fence_acq() {
    asm volatile("fence.acq_rel.gpu;" ::: "memory");
}
__device__ __forceinline__ void fence_pa() {
    asm volatile("fence.proxy.async;" ::: "memory");
}
__device__ __forceinline__ void announce(unsigned* p) {
    __syncthreads();
    if (threadIdx.x == 0) red_rel(p);
}
__device__ __forceinline__ void gbar(unsigned target) {
    __syncthreads();
    if (threadIdx.x == 0) {
        red_rel(&g_count);
        while (ld_rlx(&g_count) < target) { }
        fence_acq();
    }
    __syncthreads();
}

// ---------------- mbarrier / bulk copy ----------------
__device__ __forceinline__ void mbar_init(uint32_t a, unsigned cnt) {
    asm volatile("mbarrier.init.shared.b64 [%0], %1;" :: "r"(a), "r"(cnt) : "memory");
}
__device__ __forceinline__ void mbar_expect(uint32_t a, unsigned bytes) {
    asm volatile("mbarrier.arrive.expect_tx.shared.b64 _, [%0], %1;"
                 :: "r"(a), "r"(bytes) : "memory");
}
__device__ __forceinline__ void mbar_wait(uint32_t a, unsigned par) {
    unsigned done;
    do {
        asm volatile(
            "{\n\t.reg .pred p;\n\t"
            "mbarrier.try_wait.parity.shared.b64 p, [%1], %2, 0x989680;\n\t"
            "selp.b32 %0, 1, 0, p;\n\t}"
            : "=r"(done) : "r"(a), "r"(par) : "memory");
    } while (!done);
}
__device__ __forceinline__ void bulk_g2s(uint32_t dst, const void* src,
                                         unsigned bytes, uint32_t mbar) {
    asm volatile(
        "cp.async.bulk.shared::cta.global.mbarrier::complete_tx::bytes "
        "[%0], [%1], %2, [%3];"
        :: "r"(dst), "l"(src), "r"(bytes), "r"(mbar) : "memory");
}

// bf16 split helpers
__device__ __forceinline__ unsigned pack_pair_hi(float e, float o,
                                                 float& re, float& ro) {
    __nv_bfloat16 he = __float2bfloat16(e);
    __nv_bfloat16 ho = __float2bfloat16(o);
    re = e - __bfloat162float(he);
    ro = o - __bfloat162float(ho);
    return ((unsigned)__bfloat16_as_ushort(ho) << 16) |
           (unsigned)__bfloat16_as_ushort(he);
}
__device__ __forceinline__ unsigned pack_pair(float e, float o) {
    __nv_bfloat16 he = __float2bfloat16(e);
    __nv_bfloat16 ho = __float2bfloat16(o);
    return ((unsigned)__bfloat16_as_ushort(ho) << 16) |
           (unsigned)__bfloat16_as_ushort(he);
}

#define MMA16816(cr, a0_, a1_, a2_, a3_, b0_, b1_)                          \
    asm volatile("mma.sync.aligned.m16n8k16.row.col.f32.bf16.bf16.f32 "     \
        "{%0,%1,%2,%3}, {%4,%5,%6,%7}, {%8,%9}, {%0,%1,%2,%3};"             \
        : "+f"((cr)[0]), "+f"((cr)[1]), "+f"((cr)[2]), "+f"((cr)[3])        \
        : "r"(a0_), "r"(a1_), "r"(a2_), "r"(a3_), "r"(b0_), "r"(b1_))

// ---------------- reset (graph-replay determinism) ----------------
__global__ void reset_kernel() {
    int i = threadIdx.x;
    if (i == 0) g_count = 0;
    if (i < NBC * 32) g_hbc[i] = 0;
}

// hi passes (hi*Whi + hi*Wlo) for one 16-row m-tile from buffer sb
#define P12(sb_, mt_)                                                        \
{                                                                            \
    _Pragma("unroll")                                                        \
    for (int q_ = 0; q_ < 8; q_++) {                                         \
        int kqb_ = 64 * warp + 8 * q_;                                       \
        int w0_ = kqb_ + la4;                                                \
        unsigned a0_ = (sb_)[ld4 * HPITCH + w0_];                            \
        unsigned a1_ = (sb_)[(ld4 + 8) * HPITCH + w0_];                      \
        unsigned a2_ = (sb_)[ld4 * HPITCH + (w0_ ^ 4)];                      \
        unsigned a3_ = (sb_)[(ld4 + 8) * HPITCH + (w0_ ^ 4)];                \
        _Pragma("unroll")                                                    \
        for (int nt_ = 0; nt_ < 4; nt_++) {                                  \
            int colW_ = (8 * nt_ + ld4) ^ (la4 << 3);                        \
            unsigned bh0_ = wh[w0_ * 32 + colW_];                            \
            unsigned bh1_ = wh[(w0_ + 4) * 32 + colW_];                      \
            unsigned bl0_ = wl[w0_ * 32 + colW_];                            \
            unsigned bl1_ = wl[(w0_ + 4) * 32 + colW_];                      \
            MMA16816(C[mt_][nt_], a0_, a1_, a2_, a3_, bh0_, bh1_);           \
            MMA16816(C[mt_][nt_], a0_, a1_, a2_, a3_, bl0_, bl1_);           \
        }                                                                    \
    }                                                                        \
}

// lo pass (lo*Whi) for one m-tile from buffer sb
#define P3(sb_, mt_)                                                         \
{                                                                            \
    _Pragma("unroll")                                                        \
    for (int q_ = 0; q_ < 8; q_++) {                                         \
        int kqb_ = 64 * warp + 8 * q_;                                       \
        int w0_ = kqb_ + la4;                                                \
        unsigned a0_ = (sb_)[ld4 * HPITCH + w0_];                            \
        unsigned a1_ = (sb_)[(ld4 + 8) * HPITCH + w0_];                      \
        unsigned a2_ = (sb_)[ld4 * HPITCH + (w0_ ^ 4)];                      \
        unsigned a3_ = (sb_)[(ld4 + 8) * HPITCH + (w0_ ^ 4)];                \
        _Pragma("unroll")                                                    \
        for (int nt_ = 0; nt_ < 4; nt_++) {                                  \
            int colW_ = (8 * nt_ + ld4) ^ (la4 << 3);                        \
            unsigned bh0_ = wh[w0_ * 32 + colW_];                            \
            unsigned bh1_ = wh[(w0_ + 4) * 32 + colW_];                      \
            MMA16816(C[mt_][nt_], a0_, a1_, a2_, a3_, bh0_, bh1_);           \
        }                                                                    \
    }                                                                        \
}

// ---------------- the single persistent kernel ----------------
__global__ void __launch_bounds__(NTHR, 1) mega_kernel(
        const float* __restrict__ stim,
        const float* __restrict__ ctx,
        const float* __restrict__ w_rec,
        const float* __restrict__ b_rec,
        const float* __restrict__ w_in,
        const float* __restrict__ w_ctx,
        const float* __restrict__ w_out,
        const float* __restrict__ b_out,
        const float* __restrict__ c1_w,
        const float* __restrict__ c1_b,
        const float* __restrict__ c2_w,
        const float* __restrict__ c2_b,
        const float* __restrict__ noise,
        float* __restrict__ out0,
        float* __restrict__ acts,
        float* __restrict__ pout) {
    extern __shared__ float sm[];
    unsigned* wh = (unsigned*)(sm + SM_WH);      // [512 kq][32 j] swizzled
    unsigned* wl = (unsigned*)(sm + SM_WL);
    const unsigned* bufA = (const unsigned*)(sm + SM_ST);
    const unsigned* bufB = (const unsigned*)(sm + SM_BUFB);

    const int c    = blockIdx.x;
    const int tid  = threadIdx.x;
    const int lane = tid & 31;
    const int warp = tid >> 5;
    const int la4 = lane & 3, ld4 = lane >> 2;
    // tile roles
    const int bc = c >> 5;               // batch group 0..3 (32 b rows)
    const int jc = c & 31;               // j slice 0..31 (32 j cols)
    const int bc32 = bc * 32;
    // per-thread output mapping
    const int bl  = tid >> 3;            // 0..31
    const int jql = tid & 7;             // 0..7
    const int bglob = 32 * bc + bl;
    const int jgl = 32 * jc + jql * 4;   // global j base (multiple of 4)

    const uint32_t stA = (uint32_t)__cvta_generic_to_shared(sm + SM_ST);
    const uint32_t stB = (uint32_t)__cvta_generic_to_shared(sm + SM_BUFB);
    const uint32_t mbA = (uint32_t)__cvta_generic_to_shared(sm + SM_MBAR);
    const uint32_t mbB = mbA + 8;

    if (tid == 0) {
        mbar_init(mbA, 1);
        mbar_init(mbB, 1);
        asm volatile("fence.proxy.async.shared::cta;" ::: "memory");
    }

    // ---- P0a: classifier fusion ----
    {
        int idx = c * NTHR + tid;
        if (idx < NOUTn * Hn) g_comb[idx] = w_out[idx];
        if (idx < NCLSn * CLSOUTn * Hn) {
            int r = idx / Hn, h = idx % Hn;
            int j = r / CLSOUTn, o = r % CLSOUTn;
            float acc = 0.f;
            #pragma unroll
            for (int k = 0; k < BOTn; k++)
                acc += c2_w[(j * CLSOUTn + o) * BOTn + k] * c1_w[(j * BOTn + k) * Hn + h];
            g_comb[(NOUTn + r) * Hn + h] = acc;
        }
        if (idx < NOUTn) g_combb[idx] = b_out[idx];
        if (idx >= NOUTn && idx < NR) {
            int r = idx - NOUTn;
            int j = r / CLSOUTn, o = r % CLSOUTn;
            float acc = c2_b[j * CLSOUTn + o];
            #pragma unroll
            for (int k = 0; k < BOTn; k++)
                acc += c2_w[(j * CLSOUTn + o) * BOTn + k] * c1_b[j * BOTn + k];
            g_combb[idx] = acc;
        }
    }

    // ---- P0b: W columns [32jc, +32), all k, hi/lo bf16 k-pairs (swizzled) ----
    for (int idx = tid; idx < 512 * 32; idx += NTHR) {
        int kq = idx >> 5, jl = idx & 31;
        int j = 32 * jc + jl;
        int k0 = 2 * kq;
        float w0 = fmaxf(w_rec[(size_t)k0 * Hn + j], 0.f);
        float w1 = fmaxf(w_rec[(size_t)(k0 + 1) * Hn + j], 0.f);
        if (k0 == j) w0 = 0.f;
        if (k0 + 1 == j) w1 = 0.f;
        w0 = (k0 < NEXC) ? w0 : -w0;
        w1 = (k0 + 1 < NEXC) ? w1 : -w1;
        float r0, r1;
        int sidx = kq * 32 + (jl ^ ((kq & 3) << 3));
        wh[sidx] = pack_pair_hi(w0, w1, r0, r1);
        wl[sidx] = pack_pair(r0, r1);
    }
    float br[4];
    #pragma unroll
    for (int jj = 0; jj < 4; jj++) br[jj] = b_rec[jgl + jj];

    // ---- P0c: h_post(0) = 0 (b-major padded pairs), announce ----
    {
        int kq0 = jgl >> 1;
        g_hph[0][(size_t)bglob * HPITCH + kq0]     = 0u;
        g_hph[0][(size_t)bglob * HPITCH + kq0 + 1] = 0u;
        g_hpl[0][(size_t)bglob * HPITCH + kq0]     = 0u;
        g_hpl[0][(size_t)bglob * HPITCH + kq0 + 1] = 0u;
    }
    announce(&g_hbc[bc32]);

    // ---- P1: drive precompute ([t][h][b]) ----
    {
        const int gg = tid >> 7;
        const int bbb = tid & 127;
        for (int u = c; u < Tn * 4; u += NCTA) {
            const int t = u % Tn;
            const int h0 = (u / Tn) * 256 + gg * 128;

            float sin_r[Sn], cin_r[Cn];
            const float4* sp = (const float4*)(stim + ((size_t)bbb * Tn + t) * Sn);
            #pragma unroll
            for (int p = 0; p < Sn / 4; p++) {
                float4 v = sp[p];
                sin_r[4*p] = v.x; sin_r[4*p+1] = v.y; sin_r[4*p+2] = v.z; sin_r[4*p+3] = v.w;
            }
            const float4* cpp = (const float4*)(ctx + ((size_t)bbb * Tn + t) * Cn);
            #pragma unroll
            for (int p = 0; p < Cn / 4; p++) {
                float4 v = cpp[p];
                cin_r[4*p] = v.x; cin_r[4*p+1] = v.y; cin_r[4*p+2] = v.z; cin_r[4*p+3] = v.w;
            }
            const float4* nzp = (const float4*)(noise + ((size_t)t * Bn + bbb) * Hn);

            for (int hh = 0; hh < 128; hh += 4) {
                const int h = h0 + hh;
                float acc0 = 0.f, acc1 = 0.f, acc2 = 0.f, acc3 = 0.f;
                #pragma unroll
                for (int s4 = 0; s4 < Sn / 4; s4++) {
                    float4 w0 = *(const float4*)(w_in + (size_t)(h + 0) * Sn + s4 * 4);
                    float4 w1 = *(const float4*)(w_in + (size_t)(h + 1) * Sn + s4 * 4);
                    float4 w2 = *(const float4*)(w_in + (size_t)(h + 2) * Sn + s4 * 4);
                    float4 w3 = *(const float4*)(w_in + (size_t)(h + 3) * Sn + s4 * 4);
                    float i0 = sin_r[4*s4], i1 = sin_r[4*s4+1];
                    float i2 = sin_r[4*s4+2], i3 = sin_r[4*s4+3];
                    acc0 = fmaf(i0, w0.x, acc0); acc0 = fmaf(i1, w0.y, acc0);
                    acc0 = fmaf(i2, w0.z, acc0); acc0 = fmaf(i3, w0.w, acc0);
                    acc1 = fmaf(i0, w1.x, acc1); acc1 = fmaf(i1, w1.y, acc1);
                    acc1 = fmaf(i2, w1.z, acc1); acc1 = fmaf(i3, w1.w, acc1);
                    acc2 = fmaf(i0, w2.x, acc2); acc2 = fmaf(i1, w2.y, acc2);
                    acc2 = fmaf(i2, w2.z, acc2); acc2 = fmaf(i3, w2.w, acc2);
                    acc3 = fmaf(i0, w3.x, acc3); acc3 = fmaf(i1, w3.y, acc3);
                    acc3 = fmaf(i2, w3.z, acc3); acc3 = fmaf(i3, w3.w, acc3);
                }
                #pragma unroll
                for (int c4 = 0; c4 < Cn / 4; c4++) {
                    float4 w0 = *(const float4*)(w_ctx + (size_t)(h + 0) * Cn + c4 * 4);
                    float4 w1 = *(const float4*)(w_ctx + (size_t)(h + 1) * Cn + c4 * 4);
                    float4 w2 = *(const float4*)(w_ctx + (size_t)(h + 2) * Cn + c4 * 4);
                    float4 w3 = *(const float4*)(w_ctx + (size_t)(h + 3) * Cn + c4 * 4);
                    float i0 = cin_r[4*c4], i1 = cin_r[4*c4+1];
                    float i2 = cin_r[4*c4+2], i3 = cin_r[4*c4+3];
                    acc0 = fmaf(i0, w0.x, acc0); acc0 = fmaf(i1, w0.y, acc0);
                    acc0 = fmaf(i2, w0.z, acc0); acc0 = fmaf(i3, w0.w, acc0);
                    acc1 = fmaf(i0, w1.x, acc1); acc1 = fmaf(i1, w1.y, acc1);
                    acc1 = fmaf(i2, w1.z, acc1); acc1 = fmaf(i3, w1.w, acc1);
                    acc2 = fmaf(i0, w2.x, acc2); acc2 = fmaf(i1, w2.y, acc2);
                    acc2 = fmaf(i2, w2.z, acc2); acc2 = fmaf(i3, w2.w, acc2);
                    acc3 = fmaf(i0, w3.x, acc3); acc3 = fmaf(i1, w3.y, acc3);
                    acc3 = fmaf(i2, w3.z, acc3); acc3 = fmaf(i3, w3.w, acc3);
                }
                float4 nz = nzp[h >> 2];
                float* gd = g_drive + ((size_t)t * Hn + h) * Bn + bbb;
                gd[0]      = fmaf(NZ_SCALE, nz.x, acc0);
                gd[Bn]     = fmaf(NZ_SCALE, nz.y, acc1);
                gd[2 * Bn] = fmaf(NZ_SCALE, nz.z, acc2);
                gd[3 * Bn] = fmaf(NZ_SCALE, nz.w, acc3);
            }
        }
    }

    gbar(NCTA);   // drive complete

    // ---- P2: scan ----
    float h[4], sx[4], su[4];
    #pragma unroll
    for (int jj = 0; jj < 4; jj++) {
        h[jj] = 0.f;
        sx[jj] = 1.f;
        su[jj] = (jj & 1) ? 0.15f : 0.45f;
    }

    for (int step = 0; step < Tn; step++) {
        const unsigned htarget = 32u * (unsigned)(step + 1);
        const int par = step & 1;

        // drive prefetch (overlaps the flag wait)
        const float* gd = g_drive + ((size_t)step * Hn + jgl) * Bn + bglob;
        float d0 = __ldcg(gd), d1 = __ldcg(gd + Bn);
        float d2 = __ldcg(gd + 2 * Bn), d3 = __ldcg(gd + 3 * Bn);

        // ---- wait: my batch group's h rows ready (RAW + WAR: closed group) ----
        if (tid == 0) {
            while (ld_rlx(&g_hbc[bc32]) < htarget) { }
            fence_acq();
            fence_pa();
        }
        __syncthreads();

        const char* srch = (const char*)(g_hph[par] + (size_t)(32 * bc) * HPITCH);
        const char* srcl = (const char*)(g_hpl[par] + (size_t)(32 * bc) * HPITCH);

        float C[2][4][4];
        #pragma unroll
        for (int mt = 0; mt < 2; mt++)
            #pragma unroll
            for (int nt = 0; nt < 4; nt++) {
                C[mt][nt][0] = 0.f; C[mt][nt][1] = 0.f;
                C[mt][nt][2] = 0.f; C[mt][nt][3] = 0.f;
            }

        if (tid == 0) {
            mbar_expect(mbA, CHUNK_BYTES);
            bulk_g2s(stA, srch, CHUNK_BYTES, mbA);                 // hi mt0
            mbar_expect(mbB, CHUNK_BYTES);
            bulk_g2s(stB, srcl, CHUNK_BYTES, mbB);                 // lo mt0
        }

        mbar_wait(mbA, 0);
        P12(bufA, 0)
        __syncthreads();
        if (tid == 0) {
            mbar_expect(mbA, CHUNK_BYTES);
            bulk_g2s(stA, srch + CHUNK_BYTES, CHUNK_BYTES, mbA);   // hi mt1
        }

        mbar_wait(mbB, 0);
        P3(bufB, 0)
        __syncthreads();
        if (tid == 0) {
            mbar_expect(mbB, CHUNK_BYTES);
            bulk_g2s(stB, srcl + CHUNK_BYTES, CHUNK_BYTES, mbB);   // lo mt1
        }

        mbar_wait(mbA, 1);
        P12(bufA, 1)
        mbar_wait(mbB, 1);
        P3(bufB, 1)
        __syncthreads();          // all MMA reads done before Cbuf aliases staging

        // ---- cross-warp k-reduce via Cbuf (aliases staging region) ----
        {
            float* cb = sm + SM_ST + warp * (32 * CPITCH);
            #pragma unroll
            for (int mt = 0; mt < 2; mt++)
                #pragma unroll
                for (int nt = 0; nt < 4; nt++) {
                    int r0 = (16 * mt + ld4) * CPITCH + 8 * nt + 2 * la4;
                    cb[r0]     = C[mt][nt][0];
                    cb[r0 + 1] = C[mt][nt][1];
                    cb[r0 + 8 * CPITCH]     = C[mt][nt][2];
                    cb[r0 + 8 * CPITCH + 1] = C[mt][nt][3];
                }
        }
        __syncthreads();

        float s0 = 0.f, s1 = 0.f, s2 = 0.f, s3 = 0.f;
        {
            const float* cbb = sm + SM_ST;
            #pragma unroll
            for (int w2 = 0; w2 < 8; w2++) {
                const float* p = cbb + w2 * (32 * CPITCH) + bl * CPITCH + jql * 4;
                s0 += p[0]; s1 += p[1]; s2 += p[2]; s3 += p[3];
            }
        }

        float ss[4] = {s0, s1, s2, s3};
        float dd[4] = {d0, d1, d2, d3};
        float hn[4], hp[4];
        #pragma unroll
        for (int jj = 0; jj < 4; jj++) {
            float val = h[jj] * (1.f - ALPHA_N)
                      + ALPHA_N * (dd[jj] + ss[jj] + br[jj]);
            hn[jj] = fmaxf(val, 0.f);
            h[jj] = hn[jj];
        }
        // STP + h_post(step+1) pairs, announce, then acts store
        #pragma unroll
        for (int jj = 0; jj < 4; jj++) {
            const float axv = (jj & 1) ? AX_FAST : AX_SLOW;
            const float Uv  = (jj & 1) ? 0.15f : 0.45f;
            float hh = h[jj];
            float sxo = sx[jj], suo = su[jj];
            float sxn = sxo + axv * (1.f - sxo) - DT_SEC * suo * sxo * hh;
            float sun = suo + axv * (Uv - suo) + DT_SEC * Uv * (1.f - suo) * hh;
            sxn = fminf(fmaxf(sxn, 0.f), 1.f);
            sun = fminf(fmaxf(sun, 0.f), 1.f);
            sx[jj] = sxn; su[jj] = sun;
            hp[jj] = sun * sxn * hh;
        }
        {
            unsigned* dh = g_hph[par ^ 1];
            unsigned* dl = g_hpl[par ^ 1];
            int kq0 = jgl >> 1;
            float r0, r1, r2, r3;
            unsigned h01 = pack_pair_hi(hp[0], hp[1], r0, r1);
            unsigned h23 = pack_pair_hi(hp[2], hp[3], r2, r3);
            dh[(size_t)bglob * HPITCH + kq0]     = h01;
            dh[(size_t)bglob * HPITCH + kq0 + 1] = h23;
            dl[(size_t)bglob * HPITCH + kq0]     = pack_pair(r0, r1);
            dl[(size_t)bglob * HPITCH + kq0 + 1] = pack_pair(r2, r3);
        }
        announce(&g_hbc[bc32]);

        *(float4*)(acts + ((size_t)bglob * Tn + step) * Hn + jgl) =
            make_float4(hn[0], hn[1], hn[2], hn[3]);
    }

    gbar(2 * NCTA);   // scan complete

    // ---- P3: post (fused readout) ----
    {
        float* s_comb = sm + SM_COMB;
        for (int i = tid; i < NR * Hn; i += NTHR) s_comb[i] = g_comb[i];
        __syncthreads();

        const float4* comb4 = (const float4*)s_comb;

        for (int u = c; u < (Bn * Tn) / PR_ROWS; u += NCTA) {
            #pragma unroll 1
            for (int rr = 0; rr < 4; rr++) {
                const int bt = u * PR_ROWS + warp * 4 + rr;
                const float4* a4 = (const float4*)(acts + (size_t)bt * Hn);

                float acc[NR];
                #pragma unroll
                for (int r = 0; r < NR; r++) acc[r] = 0.f;

                #pragma unroll
                for (int it = 0; it < Hn / 128; it++) {
                    float4 a = a4[it * 32 + lane];
                    #pragma unroll
                    for (int r = 0; r < NR; r++) {
                        float4 ww = comb4[r * 256 + it * 32 + lane];
                        float s = a.x * ww.x + a.y * ww.y;
                        s = fmaf(a.z, ww.z, s);
                        s = fmaf(a.w, ww.w, s);
                        acc[r] += s;
                    }
                }
                #pragma unroll
                for (int r = 0; r < NR; r++) {
                    #pragma unroll
                    for (int off = 16; off > 0; off >>= 1)
                        acc[r] += __shfl_down_sync(0xffffffffu, acc[r], off);
                }
                if (lane == 0) {
                    #pragma unroll
                    for (int r = 0; r < NOUTn; r++)
                        out0[(size_t)bt * NOUTn + r] = acc[r] + g_combb[r];
                    #pragma unroll
                    for (int r = NOUTn; r < NR; r++)
                        pout[(size_t)bt * (NCLSn * CLSOUTn) + (r - NOUTn)]
                            = acc[r] + g_combb[r];
                }
            }
        }
    }
}

// ---------------- launch ----------------
extern "C" void kernel_launch(void* const* d_in, const int* in_sizes, int n_in,
                              void* d_out, int out_size) {
    const float* stim  = (const float*)d_in[0];
    const float* ctx   = (const float*)d_in[1];
    const float* w_rec = (const float*)d_in[2];
    const float* b_rec = (const float*)d_in[3];
    const float* w_in  = (const float*)d_in[4];
    const float* w_ctx = (const float*)d_in[5];
    const float* w_out = (const float*)d_in[6];
    const float* b_out = (const float*)d_in[7];
    const float* c1_w  = (const float*)d_in[8];
    const float* c1_b  = (const float*)d_in[9];
    const float* c2_w  = (const float*)d_in[10];
    const float* c2_b  = (const float*)d_in[11];
    const float* noise = (const float*)d_in[12];

    float* out0 = (float*)d_out;                         // [B, T, 3]
    float* acts = out0 + (size_t)Bn * Tn * NOUTn;        // [B, T, H]
    float* pout = acts + (size_t)Bn * Tn * Hn;           // [B, T, 3, 8]

    static bool attr_set = false;
    if (!attr_set) {
        cudaFuncSetAttribute(mega_kernel,
                             cudaFuncAttributeMaxDynamicSharedMemorySize,
                             SMEM_BYTES);
        attr_set = true;
    }

    reset_kernel<<<1, 256>>>();
    mega_kernel<<<NCTA, NTHR, SMEM_BYTES>>>(
        stim, ctx, w_rec, b_rec, w_in, w_ctx, w_out, b_out,
        c1_w, c1_b, c2_w, c2_b, noise, out0, acts, pout);
}